// round 9
// baseline (speedup 1.0000x reference)
#include <cuda_runtime.h>
#include <cuda_bf16.h>
#include <cstdint>

// ---------------------------------------------------------------------------
// WindowAttention (Swin-style, faithful to the reference's raw-view scramble).
// GEMMs: tf32 mma.sync (fp32 accumulate), static smem, synchronous loads
// (structure identical to the 3173us-passing round-4 kernel). Deltas vs R4:
//   (a) GEMM grid transposed: x = n-tile (fast), y = window-pair, so a
//       concurrent wave shares each A chunk across all n-tiles via L2
//       (A DRAM traffic 2.8GB -> ~0.2GB on QKV).
//   (b) Attention uses precomputed per-head bias panels / per-window mask
//       panels and a float4 softmax.
// ---------------------------------------------------------------------------

#define BATCH   16
#define CDIM    768
#define HS      56
#define NHEADS  24
#define HD      32
#define NTOK    49
#define NWIN    64
#define BWIN    (BATCH * NWIN)      // 1024
#define WFLAT   (NTOK * CDIM)       // 37632
#define QSCALE  0.17677669529663687f

// Scratch (static device globals; allocation is banned)
__device__ float g_buf[BWIN * WFLAT];   // window-flat hwc input; later attn out (aliased)
__device__ float g_q  [BWIN * WFLAT];   // [b_][h][n][d], pre-scaled
__device__ float g_k  [BWIN * WFLAT];
__device__ float g_v  [BWIN * WFLAT];
__device__ float g_bias [NHEADS * 2560];    // per-head 49x52 bias panel (pad=-1e30)
__device__ float g_maskp[NWIN   * 2560];    // per-window 49x52 mask panel (pad=0)

// ---------------------------------------------------------------------------
__device__ __forceinline__ uint32_t f2tf(float f) {
    uint32_t u;
    asm("cvt.rna.tf32.f32 %0, %1;" : "=r"(u) : "f"(f));
    return u;
}

__device__ __forceinline__ void mma_tf32(float* c, const uint32_t* a, const uint32_t* b) {
    asm volatile(
        "mma.sync.aligned.m16n8k8.row.col.f32.tf32.tf32.f32 "
        "{%0,%1,%2,%3},{%4,%5,%6,%7},{%8,%9},{%0,%1,%2,%3};"
        : "+f"(c[0]), "+f"(c[1]), "+f"(c[2]), "+f"(c[3])
        : "r"(a[0]), "r"(a[1]), "r"(a[2]), "r"(a[3]), "r"(b[0]), "r"(b[1]));
}

// ---------------------------------------------------------------------------
// Pre-pass: bias panels per head (pad cols = -1e30) and mask panels per
// window (pad cols = 0). grid 24+64 = 88 blocks x 256.
// ---------------------------------------------------------------------------
__global__ void __launch_bounds__(256) prep_kernel(const float* __restrict__ bias_table,
                                                   const int*   __restrict__ rel_index,
                                                   const float* __restrict__ mask)
{
    int blk = blockIdx.x;
    if (blk < NHEADS) {
        int h = blk;
        for (int i = threadIdx.x; i < NTOK * 52; i += 256) {
            int r = i / 52, m = i % 52;
            float v = (m < NTOK) ? bias_table[rel_index[r * NTOK + m] * NHEADS + h] : -1e30f;
            g_bias[h * 2560 + r * 52 + m] = v;
        }
    } else {
        int w = blk - NHEADS;
        for (int i = threadIdx.x; i < NTOK * 52; i += 256) {
            int r = i / 52, m = i % 52;
            float v = (m < NTOK) ? mask[w * (NTOK * NTOK) + r * NTOK + m] : 0.0f;
            g_maskp[w * 2560 + r * 52 + m] = v;
        }
    }
}

// ---------------------------------------------------------------------------
// Kernel 1: x (B,C,H,W) -> g_buf[(b*64+win)*37632 + (i*7+j)*768 + c]
// ---------------------------------------------------------------------------
__global__ void __launch_bounds__(256) gather_kernel(const float* __restrict__ x)
{
    int bh = blockIdx.x;
    int b  = bh / HS;
    int h  = bh % HS;
    int c0 = blockIdx.y * 32;
    int tx = threadIdx.x, ty = threadIdx.y;

    __shared__ float tile[32][33];

    int wr = h / 7, ii = h % 7;

    for (int w0 = 0; w0 < HS; w0 += 32) {
        int wlim = min(32, HS - w0);
        __syncthreads();
        if (tx < wlim) {
            #pragma unroll
            for (int cy = ty; cy < 32; cy += 8)
                tile[cy][tx] = x[((b * CDIM + c0 + cy) * HS + h) * HS + w0 + tx];
        }
        __syncthreads();
        for (int wy = ty; wy < wlim; wy += 8) {
            int w   = w0 + wy;
            int win = wr * 8 + (w / 7);
            int n   = ii * 7 + (w % 7);
            g_buf[(b * NWIN + win) * WFLAT + n * CDIM + c0 + tx] = tile[tx][wy];
        }
    }
}

// ---------------------------------------------------------------------------
// Tensor-core GEMM (structure identical to R4-passing kernel).
// Block: BM=128 (2 windows x 64-pad) x BN=128, BK=32. 256 thr = 8 warps,
// warp grid 2(m) x 4(n), per-warp 4x4 m16n8k8 tiles. smem K-innermost,
// LDT=36 (conflict-free fragment loads).
// grid (Nout/128, BWIN/2): x = n-tile (FAST) -> wave shares A via L2.
// ---------------------------------------------------------------------------
#define LDT 36

template <int MODE>
__global__ void __launch_bounds__(256) gemm_tc_kernel(const float* __restrict__ W,
                                                      const float* __restrict__ bias,
                                                      float* __restrict__ out)
{
    int n0  = blockIdx.x * 128;
    int tid = threadIdx.x;
    int lane = tid & 31, warp = tid >> 5;
    int grp = lane >> 2, tig = lane & 3;
    int warp_m = warp & 1;
    int warp_n = warp >> 1;

    __shared__ uint32_t As[128 * LDT];   // [m][k], k in 0..31
    __shared__ uint32_t Bs[128 * LDT];   // [n][k]

    const float* A0 = g_buf + (size_t)(2 * blockIdx.y)     * WFLAT;
    const float* A1 = g_buf + (size_t)(2 * blockIdx.y + 1) * WFLAT;

    float acc[4][4][4];
    #pragma unroll
    for (int i = 0; i < 4; i++)
        #pragma unroll
        for (int j = 0; j < 4; j++)
            #pragma unroll
            for (int r = 0; r < 4; r++) acc[i][j][r] = 0.0f;

    for (int k0 = 0; k0 < CDIM; k0 += 32) {
        // ---- A tiles: two contiguous 49x32 chunks ([k][m] in source) ----
        const float* s0 = A0 + k0 * NTOK;
        const float* s1 = A1 + k0 * NTOK;
        #pragma unroll
        for (int it = 0; it < 7; it++) {
            int i = tid + it * 256;
            if (i < 1568) {
                int k = i / 49, m = i - k * 49;
                As[m * LDT + k]        = f2tf(s0[i]);
                As[(64 + m) * LDT + k] = f2tf(s1[i]);
            }
        }
        // ---- B tile: W rows n0..n0+127, cols k0..k0+31 ----
        #pragma unroll
        for (int it = 0; it < 4; it++) {
            int i  = tid + it * 256;
            int n  = i >> 3;
            int kq = (i & 7) << 2;
            float4 wv = *(const float4*)(W + (size_t)(n0 + n) * CDIM + k0 + kq);
            uint32_t* d = &Bs[n * LDT + kq];
            d[0] = f2tf(wv.x); d[1] = f2tf(wv.y); d[2] = f2tf(wv.z); d[3] = f2tf(wv.w);
        }
        __syncthreads();

        #pragma unroll
        for (int ks = 0; ks < 4; ks++) {
            int k8 = ks * 8;
            uint32_t bfr[4][2];
            #pragma unroll
            for (int nt = 0; nt < 4; nt++) {
                int n = warp_n * 32 + nt * 8 + grp;
                bfr[nt][0] = Bs[n * LDT + k8 + tig];
                bfr[nt][1] = Bs[n * LDT + k8 + tig + 4];
            }
            #pragma unroll
            for (int mt = 0; mt < 4; mt++) {
                uint32_t afr[4];                 // short-lived: load, 4 mma, dead
                int m = warp_m * 64 + mt * 16 + grp;
                afr[0] = As[m * LDT + k8 + tig];
                afr[1] = As[(m + 8) * LDT + k8 + tig];
                afr[2] = As[m * LDT + k8 + tig + 4];
                afr[3] = As[(m + 8) * LDT + k8 + tig + 4];
                #pragma unroll
                for (int nt = 0; nt < 4; nt++)
                    mma_tf32(acc[mt][nt], afr, bfr[nt]);
            }
        }
        __syncthreads();
    }

    // ---- epilogue ----
    #pragma unroll
    for (int nt = 0; nt < 4; nt++) {
        int n_loc = warp_n * 32 + nt * 8 + 2 * tig;
        int n_g   = n0 + n_loc;
        float2 bb = *(const float2*)&bias[n_g];

        int which = 0, h = 0, d = 0;
        float sc = 1.0f;
        float* dst0 = nullptr;
        if (MODE == 0) {
            which = n_g / CDIM;                 // constant per block
            int rem = n_g - which * CDIM;
            h = rem >> 5; d = rem & 31;
            dst0 = (which == 0) ? g_q : (which == 1 ? g_k : g_v);
            sc = (which == 0) ? QSCALE : 1.0f;
        }

        #pragma unroll
        for (int mt = 0; mt < 4; mt++) {
            #pragma unroll
            for (int half = 0; half < 2; half++) {
                int m   = warp_m * 64 + mt * 16 + grp + half * 8;
                int win = m >> 6;
                int tok = m & 63;
                if (tok < NTOK) {
                    int b_ = 2 * blockIdx.y + win;
                    float c0 = acc[mt][nt][half * 2 + 0];
                    float c1 = acc[mt][nt][half * 2 + 1];
                    if (MODE == 0) {
                        float2 o = make_float2((c0 + bb.x) * sc, (c1 + bb.y) * sc);
                        *(float2*)&dst0[((b_ * NHEADS + h) * NTOK + tok) * HD + d] = o;
                    } else {
                        float2 o = make_float2(c0 + bb.x, c1 + bb.y);
                        *(float2*)&out[(size_t)(b_ * NTOK + tok) * CDIM + n_g] = o;
                    }
                }
            }
        }
    }
}

// ---------------------------------------------------------------------------
// Fused attention per (window b_, head h). grid (1024, 24), 192 thr. fp32.
// Precomputed bias/mask panels; float4 softmax over padded 52-col rows.
// Writes g_buf[b_*37632 + (h*32+d)*49 + n] (column-major per window).
// ---------------------------------------------------------------------------
__global__ void __launch_bounds__(192) attn_kernel()
{
    int b_ = blockIdx.x;
    int h  = blockIdx.y;
    int tid = threadIdx.x;

    __shared__ float qT[32 * 52];    // [d][n], n pad 49..51 zeroed
    __shared__ float kT[32 * 52];
    __shared__ float Vs[49 * 32];    // [m][d]
    __shared__ float S [49 * 56];    // [n][m], stride 56 (float4-friendly)
    __shared__ float rinv[49];

    int base = ((b_ * NHEADS + h) * NTOK) * HD;
    if (tid < 96) {                  // zero pad columns so S pad cols are finite
        int d = tid / 3, n = 49 + tid % 3;
        qT[d * 52 + n] = 0.0f;
        kT[d * 52 + n] = 0.0f;
    }
    {
        const float4* qsrc = (const float4*)(g_q + base);
        const float4* ksrc = (const float4*)(g_k + base);
        const float4* vsrc = (const float4*)(g_v + base);
        for (int i = tid; i < 392; i += 192) {
            int n  = i >> 3;
            int d0 = (i & 7) << 2;
            float4 qv = qsrc[i];
            float4 kv = ksrc[i];
            qT[(d0 + 0) * 52 + n] = qv.x;
            qT[(d0 + 1) * 52 + n] = qv.y;
            qT[(d0 + 2) * 52 + n] = qv.z;
            qT[(d0 + 3) * 52 + n] = qv.w;
            kT[(d0 + 0) * 52 + n] = kv.x;
            kT[(d0 + 1) * 52 + n] = kv.y;
            kT[(d0 + 2) * 52 + n] = kv.z;
            kT[(d0 + 3) * 52 + n] = kv.w;
            ((float4*)Vs)[i] = vsrc[i];
        }
    }
    __syncthreads();

    // ---- S = q k^T ----
    if (tid < 169) {
        int tx = tid % 13, ty = tid / 13;
        float acc[4][4];
        #pragma unroll
        for (int i = 0; i < 4; i++)
            #pragma unroll
            for (int j = 0; j < 4; j++) acc[i][j] = 0.0f;

        #pragma unroll
        for (int d = 0; d < 32; d++) {
            float4 av = *(const float4*)&qT[d * 52 + ty * 4];
            float4 bv = *(const float4*)&kT[d * 52 + tx * 4];
            acc[0][0] += av.x * bv.x; acc[0][1] += av.x * bv.y; acc[0][2] += av.x * bv.z; acc[0][3] += av.x * bv.w;
            acc[1][0] += av.y * bv.x; acc[1][1] += av.y * bv.y; acc[1][2] += av.y * bv.z; acc[1][3] += av.y * bv.w;
            acc[2][0] += av.z * bv.x; acc[2][1] += av.z * bv.y; acc[2][2] += av.z * bv.z; acc[2][3] += av.z * bv.w;
            acc[3][0] += av.w * bv.x; acc[3][1] += av.w * bv.y; acc[3][2] += av.w * bv.z; acc[3][3] += av.w * bv.w;
        }
        #pragma unroll
        for (int i = 0; i < 4; i++) {
            int r = ty * 4 + i;
            if (r < NTOK)
                *(float4*)&S[r * 56 + tx * 4] = make_float4(acc[i][0], acc[i][1], acc[i][2], acc[i][3]);
        }
    }
    __syncthreads();

    // ---- softmax rows (float4 over 52-col padded rows) ----
    if (tid < NTOK) {
        int r = tid;
        int win = b_ & (NWIN - 1);
        const float4* mrow = (const float4*)(g_maskp + win * 2560 + r * 52);
        const float4* brow = (const float4*)(g_bias  + h   * 2560 + r * 52);
        float4* srow = (float4*)(S + r * 56);
        float mx = -1e30f;
        #pragma unroll
        for (int j = 0; j < 13; j++) {
            float4 s = srow[j], b = brow[j], mk = mrow[j];
            s.x += b.x + mk.x; s.y += b.y + mk.y;
            s.z += b.z + mk.z; s.w += b.w + mk.w;
            srow[j] = s;
            mx = fmaxf(mx, fmaxf(fmaxf(s.x, s.y), fmaxf(s.z, s.w)));
        }
        float sum = 0.0f;
        #pragma unroll
        for (int j = 0; j < 13; j++) {
            float4 s = srow[j];
            s.x = __expf(s.x - mx); s.y = __expf(s.y - mx);
            s.z = __expf(s.z - mx); s.w = __expf(s.w - mx);
            srow[j] = s;
            sum += (s.x + s.y) + (s.z + s.w);
        }
        rinv[r] = 1.0f / sum;
    }
    __syncthreads();

    // ---- O^T[d][n] = sum_m V[m][d] * P[n][m] ----
    if (tid < 104) {
        int tx = tid % 13;   // n-group
        int ty = tid / 13;   // d-group
        float acc[4][4];
        #pragma unroll
        for (int i = 0; i < 4; i++)
            #pragma unroll
            for (int j = 0; j < 4; j++) acc[i][j] = 0.0f;

        for (int m = 0; m < NTOK; m++) {
            float4 av = *(const float4*)&Vs[m * 32 + ty * 4];
            #pragma unroll
            for (int j = 0; j < 4; j++) {
                int n = tx * 4 + j;
                float p = (n < NTOK) ? S[n * 56 + m] : 0.0f;
                acc[0][j] += av.x * p;
                acc[1][j] += av.y * p;
                acc[2][j] += av.z * p;
                acc[3][j] += av.w * p;
            }
        }
        float* ob = g_buf + (size_t)b_ * WFLAT + (h * HD) * NTOK;
        #pragma unroll
        for (int j = 0; j < 4; j++) {
            int n = tx * 4 + j;
            if (n < NTOK) {
                float iv = rinv[n];
                #pragma unroll
                for (int i = 0; i < 4; i++)
                    ob[(ty * 4 + i) * NTOK + n] = acc[i][j] * iv;
            }
        }
    }
}

// ---------------------------------------------------------------------------
extern "C" void kernel_launch(void* const* d_in, const int* in_sizes, int n_in,
                              void* d_out, int out_size)
{
    const float* x          = (const float*)d_in[0];
    const float* mask       = (const float*)d_in[1];
    const float* qkv_w      = (const float*)d_in[2];
    const float* qkv_b      = (const float*)d_in[3];
    const float* proj_w     = (const float*)d_in[4];
    const float* proj_b     = (const float*)d_in[5];
    const float* bias_table = (const float*)d_in[6];
    const int*   rel_index  = (const int*)d_in[7];
    float* out = (float*)d_out;

    prep_kernel<<<NHEADS + NWIN, 256>>>(bias_table, rel_index, mask);
    gather_kernel<<<dim3(BATCH * HS, CDIM / 32), dim3(32, 8)>>>(x);
    gemm_tc_kernel<0><<<dim3((3 * CDIM) / 128, BWIN / 2), 256>>>(qkv_w, qkv_b, nullptr);
    attn_kernel<<<dim3(BWIN, NHEADS), 192>>>();
    gemm_tc_kernel<1><<<dim3(CDIM / 128, BWIN / 2), 256>>>(proj_w, proj_b, out);
}

// round 11
// speedup vs baseline: 1.1148x; 1.1148x over previous
#include <cuda_runtime.h>
#include <cuda_bf16.h>
#include <cstdint>

// ---------------------------------------------------------------------------
// WindowAttention (Swin-style, faithful to the reference's raw-view scramble).
// Byte-identical to the 3173us round-4 pass EXCEPT one change:
//   GEMM grid transposed: x = n-tile (fast), y = window-pair, so a concurrent
//   wave shares each per-window A chunk across all n-tiles via L2
//   (A DRAM traffic: QKV 2.8GB -> ~0.2GB, proj 0.92GB -> ~0.2GB).
// ---------------------------------------------------------------------------

#define BATCH   16
#define CDIM    768
#define HS      56
#define NHEADS  24
#define HD      32
#define NTOK    49
#define NWIN    64
#define BWIN    (BATCH * NWIN)      // 1024
#define WFLAT   (NTOK * CDIM)       // 37632
#define QSCALE  0.17677669529663687f

// Scratch (static device globals; allocation is banned)
__device__ float g_buf[BWIN * WFLAT];   // window-flat hwc input; later attn out (aliased)
__device__ float g_q  [BWIN * WFLAT];   // [b_][h][n][d], pre-scaled
__device__ float g_k  [BWIN * WFLAT];
__device__ float g_v  [BWIN * WFLAT];

// ---------------------------------------------------------------------------
__device__ __forceinline__ uint32_t f2tf(float f) {
    uint32_t u;
    asm("cvt.rna.tf32.f32 %0, %1;" : "=r"(u) : "f"(f));
    return u;
}

__device__ __forceinline__ void mma_tf32(float* c, const uint32_t* a, const uint32_t* b) {
    asm volatile(
        "mma.sync.aligned.m16n8k8.row.col.f32.tf32.tf32.f32 "
        "{%0,%1,%2,%3},{%4,%5,%6,%7},{%8,%9},{%0,%1,%2,%3};"
        : "+f"(c[0]), "+f"(c[1]), "+f"(c[2]), "+f"(c[3])
        : "r"(a[0]), "r"(a[1]), "r"(a[2]), "r"(a[3]), "r"(b[0]), "r"(b[1]));
}

// ---------------------------------------------------------------------------
// Kernel 1: x (B,C,H,W) -> g_buf[(b*64+win)*37632 + (i*7+j)*768 + c]
// ---------------------------------------------------------------------------
__global__ void __launch_bounds__(256) gather_kernel(const float* __restrict__ x)
{
    int bh = blockIdx.x;
    int b  = bh / HS;
    int h  = bh % HS;
    int c0 = blockIdx.y * 32;
    int tx = threadIdx.x, ty = threadIdx.y;

    __shared__ float tile[32][33];

    int wr = h / 7, ii = h % 7;

    for (int w0 = 0; w0 < HS; w0 += 32) {
        int wlim = min(32, HS - w0);
        __syncthreads();
        if (tx < wlim) {
            #pragma unroll
            for (int cy = ty; cy < 32; cy += 8)
                tile[cy][tx] = x[((b * CDIM + c0 + cy) * HS + h) * HS + w0 + tx];
        }
        __syncthreads();
        for (int wy = ty; wy < wlim; wy += 8) {
            int w   = w0 + wy;
            int win = wr * 8 + (w / 7);
            int n   = ii * 7 + (w % 7);
            g_buf[(b * NWIN + win) * WFLAT + n * CDIM + c0 + tx] = tile[tx][wy];
        }
    }
}

// ---------------------------------------------------------------------------
// Tensor-core GEMM (identical to R4-passing kernel except grid transpose).
// Block: BM=128 (2 windows x 64-pad) x BN=128, BK=32. 256 thr = 8 warps,
// warp grid 2(m) x 4(n), per-warp 4x4 m16n8k8 tiles. smem K-innermost,
// LDT=36 (conflict-free fragment loads).
// grid (Nout/128, BWIN/2): x = n-tile (FAST) -> wave shares A via L2.
// ---------------------------------------------------------------------------
#define LDT 36

template <int MODE>
__global__ void __launch_bounds__(256) gemm_tc_kernel(const float* __restrict__ W,
                                                      const float* __restrict__ bias,
                                                      float* __restrict__ out)
{
    int n0  = blockIdx.x * 128;
    int tid = threadIdx.x;
    int lane = tid & 31, warp = tid >> 5;
    int grp = lane >> 2, tig = lane & 3;
    int warp_m = warp & 1;          // 2
    int warp_n = warp >> 1;         // 4

    __shared__ uint32_t As[128 * LDT];   // [m][k], k in 0..31
    __shared__ uint32_t Bs[128 * LDT];   // [n][k]

    const float* A0 = g_buf + (size_t)(2 * blockIdx.y)     * WFLAT;
    const float* A1 = g_buf + (size_t)(2 * blockIdx.y + 1) * WFLAT;

    float acc[4][4][4];
    #pragma unroll
    for (int i = 0; i < 4; i++)
        #pragma unroll
        for (int j = 0; j < 4; j++)
            #pragma unroll
            for (int r = 0; r < 4; r++) acc[i][j][r] = 0.0f;

    for (int k0 = 0; k0 < CDIM; k0 += 32) {
        // ---- A tiles: two contiguous 49x32 chunks ([k][m] in source) ----
        const float* s0 = A0 + k0 * NTOK;
        const float* s1 = A1 + k0 * NTOK;
        #pragma unroll
        for (int it = 0; it < 7; it++) {
            int i = tid + it * 256;
            if (i < 1568) {
                int k = i / 49, m = i - k * 49;
                As[m * LDT + k]        = f2tf(s0[i]);
                As[(64 + m) * LDT + k] = f2tf(s1[i]);
            }
        }
        // ---- B tile: W rows n0..n0+127, cols k0..k0+31 ----
        #pragma unroll
        for (int it = 0; it < 4; it++) {
            int i  = tid + it * 256;
            int n  = i >> 3;
            int kq = (i & 7) << 2;
            float4 wv = *(const float4*)(W + (size_t)(n0 + n) * CDIM + k0 + kq);
            uint32_t* d = &Bs[n * LDT + kq];
            d[0] = f2tf(wv.x); d[1] = f2tf(wv.y); d[2] = f2tf(wv.z); d[3] = f2tf(wv.w);
        }
        __syncthreads();

        #pragma unroll
        for (int ks = 0; ks < 4; ks++) {
            int k8 = ks * 8;
            uint32_t afr[4][4], bfr[4][2];
            #pragma unroll
            for (int mt = 0; mt < 4; mt++) {
                int m = warp_m * 64 + mt * 16 + grp;
                afr[mt][0] = As[m * LDT + k8 + tig];
                afr[mt][1] = As[(m + 8) * LDT + k8 + tig];
                afr[mt][2] = As[m * LDT + k8 + tig + 4];
                afr[mt][3] = As[(m + 8) * LDT + k8 + tig + 4];
            }
            #pragma unroll
            for (int nt = 0; nt < 4; nt++) {
                int n = warp_n * 32 + nt * 8 + grp;
                bfr[nt][0] = Bs[n * LDT + k8 + tig];
                bfr[nt][1] = Bs[n * LDT + k8 + tig + 4];
            }
            #pragma unroll
            for (int mt = 0; mt < 4; mt++)
                #pragma unroll
                for (int nt = 0; nt < 4; nt++)
                    mma_tf32(acc[mt][nt], afr[mt], bfr[nt]);
        }
        __syncthreads();
    }

    // ---- epilogue ----
    #pragma unroll
    for (int nt = 0; nt < 4; nt++) {
        int n_loc = warp_n * 32 + nt * 8 + 2 * tig;
        int n_g   = n0 + n_loc;
        float2 bb = *(const float2*)&bias[n_g];

        int which = 0, h = 0, d = 0;
        float sc = 1.0f;
        float* dst0 = nullptr;
        if (MODE == 0) {
            which = n_g / CDIM;                 // constant per block
            int rem = n_g - which * CDIM;
            h = rem >> 5; d = rem & 31;
            dst0 = (which == 0) ? g_q : (which == 1 ? g_k : g_v);
            sc = (which == 0) ? QSCALE : 1.0f;
        }

        #pragma unroll
        for (int mt = 0; mt < 4; mt++) {
            #pragma unroll
            for (int half = 0; half < 2; half++) {
                int m   = warp_m * 64 + mt * 16 + grp + half * 8;
                int win = m >> 6;
                int tok = m & 63;
                if (tok < NTOK) {
                    int b_ = 2 * blockIdx.y + win;
                    float c0 = acc[mt][nt][half * 2 + 0];
                    float c1 = acc[mt][nt][half * 2 + 1];
                    if (MODE == 0) {
                        float2 o = make_float2((c0 + bb.x) * sc, (c1 + bb.y) * sc);
                        *(float2*)&dst0[((b_ * NHEADS + h) * NTOK + tok) * HD + d] = o;
                    } else {
                        float2 o = make_float2(c0 + bb.x, c1 + bb.y);
                        *(float2*)&out[(size_t)(b_ * NTOK + tok) * CDIM + n_g] = o;
                    }
                }
            }
        }
    }
}

// ---------------------------------------------------------------------------
// Fused attention per (window b_, head h). grid (1024, 24), 192 thr. fp32.
// (identical to R4 pass)
// ---------------------------------------------------------------------------
__global__ void __launch_bounds__(192) attn_kernel(const float* __restrict__ mask,
                                                   const float* __restrict__ bias_table,
                                                   const int*   __restrict__ rel_index)
{
    int b_ = blockIdx.x;
    int h  = blockIdx.y;
    int tid = threadIdx.x;

    __shared__ float qT[32 * 52];    // [d][n]
    __shared__ float kT[32 * 52];
    __shared__ float Vs[49 * 32];    // [m][d]
    __shared__ float S [52 * 53];    // [n][m]
    __shared__ float rinv[52];

    int base = ((b_ * NHEADS + h) * NTOK) * HD;
    {
        const float4* qsrc = (const float4*)(g_q + base);
        const float4* ksrc = (const float4*)(g_k + base);
        const float4* vsrc = (const float4*)(g_v + base);
        for (int i = tid; i < 392; i += 192) {
            int n  = i >> 3;
            int d0 = (i & 7) << 2;
            float4 qv = qsrc[i];
            float4 kv = ksrc[i];
            qT[(d0 + 0) * 52 + n] = qv.x;
            qT[(d0 + 1) * 52 + n] = qv.y;
            qT[(d0 + 2) * 52 + n] = qv.z;
            qT[(d0 + 3) * 52 + n] = qv.w;
            kT[(d0 + 0) * 52 + n] = kv.x;
            kT[(d0 + 1) * 52 + n] = kv.y;
            kT[(d0 + 2) * 52 + n] = kv.z;
            kT[(d0 + 3) * 52 + n] = kv.w;
            ((float4*)Vs)[i] = vsrc[i];
        }
    }
    __syncthreads();

    if (tid < 169) {
        int tx = tid % 13, ty = tid / 13;
        float acc[4][4];
        #pragma unroll
        for (int i = 0; i < 4; i++)
            #pragma unroll
            for (int j = 0; j < 4; j++) acc[i][j] = 0.0f;

        #pragma unroll
        for (int d = 0; d < 32; d++) {
            float4 av = *(const float4*)&qT[d * 52 + ty * 4];
            float4 bv = *(const float4*)&kT[d * 52 + tx * 4];
            acc[0][0] += av.x * bv.x; acc[0][1] += av.x * bv.y; acc[0][2] += av.x * bv.z; acc[0][3] += av.x * bv.w;
            acc[1][0] += av.y * bv.x; acc[1][1] += av.y * bv.y; acc[1][2] += av.y * bv.z; acc[1][3] += av.y * bv.w;
            acc[2][0] += av.z * bv.x; acc[2][1] += av.z * bv.y; acc[2][2] += av.z * bv.z; acc[2][3] += av.z * bv.w;
            acc[3][0] += av.w * bv.x; acc[3][1] += av.w * bv.y; acc[3][2] += av.w * bv.z; acc[3][3] += av.w * bv.w;
        }
        #pragma unroll
        for (int i = 0; i < 4; i++) {
            int r = ty * 4 + i;
            if (r < NTOK) {
                #pragma unroll
                for (int j = 0; j < 4; j++) S[r * 53 + tx * 4 + j] = acc[i][j];
            }
        }
    }
    __syncthreads();

    if (tid < NTOK) {
        int r = tid;
        int win = b_ & (NWIN - 1);
        const float* mrow = mask + ((size_t)win * NTOK + r) * NTOK;
        const int*   rrow = rel_index + r * NTOK;
        float mx = -1e30f;
        for (int m = 0; m < NTOK; m++) {
            float s = S[r * 53 + m] + bias_table[rrow[m] * NHEADS + h] + mrow[m];
            S[r * 53 + m] = s;
            mx = fmaxf(mx, s);
        }
        float sum = 0.0f;
        for (int m = 0; m < NTOK; m++) {
            float e = __expf(S[r * 53 + m] - mx);
            S[r * 53 + m] = e;
            sum += e;
        }
        rinv[r] = 1.0f / sum;
    }
    __syncthreads();

    if (tid < 104) {
        int tx = tid % 13;   // n-group
        int ty = tid / 13;   // d-group
        float acc[4][4];
        #pragma unroll
        for (int i = 0; i < 4; i++)
            #pragma unroll
            for (int j = 0; j < 4; j++) acc[i][j] = 0.0f;

        for (int m = 0; m < NTOK; m++) {
            float4 av = *(const float4*)&Vs[m * 32 + ty * 4];
            #pragma unroll
            for (int j = 0; j < 4; j++) {
                int n = tx * 4 + j;
                float p = (n < NTOK) ? S[n * 53 + m] : 0.0f;
                acc[0][j] += av.x * p;
                acc[1][j] += av.y * p;
                acc[2][j] += av.z * p;
                acc[3][j] += av.w * p;
            }
        }
        float* ob = g_buf + (size_t)b_ * WFLAT + (h * HD) * NTOK;
        #pragma unroll
        for (int j = 0; j < 4; j++) {
            int n = tx * 4 + j;
            if (n < NTOK) {
                float iv = rinv[n];
                #pragma unroll
                for (int i = 0; i < 4; i++)
                    ob[(ty * 4 + i) * NTOK + n] = acc[i][j] * iv;
            }
        }
    }
}

// ---------------------------------------------------------------------------
extern "C" void kernel_launch(void* const* d_in, const int* in_sizes, int n_in,
                              void* d_out, int out_size)
{
    const float* x          = (const float*)d_in[0];
    const float* mask       = (const float*)d_in[1];
    const float* qkv_w      = (const float*)d_in[2];
    const float* qkv_b      = (const float*)d_in[3];
    const float* proj_w     = (const float*)d_in[4];
    const float* proj_b     = (const float*)d_in[5];
    const float* bias_table = (const float*)d_in[6];
    const int*   rel_index  = (const int*)d_in[7];
    float* out = (float*)d_out;

    gather_kernel<<<dim3(BATCH * HS, CDIM / 32), dim3(32, 8)>>>(x);
    gemm_tc_kernel<0><<<dim3((3 * CDIM) / 128, BWIN / 2), 256>>>(qkv_w, qkv_b, nullptr);
    attn_kernel<<<dim3(BWIN, NHEADS), 192>>>(mask, bias_table, rel_index);
    gemm_tc_kernel<1><<<dim3(CDIM / 128, BWIN / 2), 256>>>(proj_w, proj_b, out);
}